// round 10
// baseline (speedup 1.0000x reference)
#include <cuda_runtime.h>

// Per-node weight accumulator. Zero at module load; phase 2 re-zeroes after
// consuming, so every graph replay starts from zeros.
__device__ __align__(16) float g_w[4 * 1024 * 1024];
__device__ double g_acc[8];
__device__ unsigned int g_count;

// ---------------- Phase 1: det(J) scattered to node weights + L2 prefetch ---
// Grid-stride, atomics interleaved per iteration (measured-best shape).
// Also prefetches the nodal_values array into L2 so phase 2's 32 MB stream
// becomes L2 hits instead of DRAM (phase 1 has idle DRAM/issue capacity).
__global__ __launch_bounds__(256) void phase1_kernel(
    const float* __restrict__ coords,    // (N_NODES, 2)
    const int*   __restrict__ elements,  // (E, 3)
    const char*  __restrict__ vals_raw,  // nodal_values as bytes (for prefetch)
    int n_elements, int n_val_lines)
{
    const int T = gridDim.x * blockDim.x;
    const int t = blockIdx.x * blockDim.x + threadIdx.x;

    // L2 prefetch of the phase-2 value stream (128B lines, grid-strided).
    for (int line = t; line < n_val_lines; line += T) {
        const char* p = vals_raw + (unsigned long long)line * 128ull;
        asm volatile("prefetch.global.L2 [%0];" :: "l"(p));
    }

    for (int e = t; e < n_elements; e += T) {
        const int i0 = __ldcs(elements + 3 * e + 0);
        const int i1 = __ldcs(elements + 3 * e + 1);
        const int i2 = __ldcs(elements + 3 * e + 2);

        const float2 c0 = *reinterpret_cast<const float2*>(coords + 2 * i0);
        const float2 c1 = *reinterpret_cast<const float2*>(coords + 2 * i1);
        const float2 c2 = *reinterpret_cast<const float2*>(coords + 2 * i2);

        // det(J) for Tri3; quad weight 1/6 folded into finalize.
        const float det = (c1.x - c0.x) * (c2.y - c0.y)
                        - (c1.y - c0.y) * (c2.x - c0.x);

        atomicAdd(&g_w[i0], det);   // REDG.F32, no return
        atomicAdd(&g_w[i1], det);
        atomicAdd(&g_w[i2], det);
    }
}

// ---------------- Phase 2: dense dot  out[v] = (1/6) sum_n w[n]*vals[n][v] ---
// nodal_values viewed as 2*N float4s. Even float4 j -> v0..3 of node j/2,
// odd j -> v4..7. Thread parity == j parity (stride is even), so each thread
// always accumulates the same 4-value group; xor-reduce preserves parity.
static const int P2_UNROLL = 8;

__global__ __launch_bounds__(256) void phase2_kernel(
    const float4* __restrict__ vals4,  // 2*N_NODES float4s
    float* __restrict__ out,
    int n_f4, int nblocks)
{
    const int T = nblocks * 256;  // total threads (even)
    const int t = blockIdx.x * 256 + threadIdx.x;

    // Front-batched guarded loads: up to 16 independent loads in flight.
    float  wreg[P2_UNROLL];
    float4 vreg[P2_UNROLL];
#pragma unroll
    for (int k = 0; k < P2_UNROLL; k++) {
        const int j = t + k * T;
        if (j < n_f4) {
            wreg[k] = g_w[j >> 1];
            vreg[k] = vals4[j];
        } else {
            wreg[k] = 0.0f;
            vreg[k] = make_float4(0.f, 0.f, 0.f, 0.f);
        }
    }

    // Zero w for next replay: even threads own even j = 2n -> every node once.
    if ((t & 1) == 0) {
#pragma unroll
        for (int k = 0; k < P2_UNROLL; k++) {
            const int j = t + k * T;
            if (j < n_f4) g_w[j >> 1] = 0.0f;
        }
    }

    float4 acc = make_float4(0.f, 0.f, 0.f, 0.f);
#pragma unroll
    for (int k = 0; k < P2_UNROLL; k++) {
        acc.x += wreg[k] * vreg[k].x;
        acc.y += wreg[k] * vreg[k].y;
        acc.z += wreg[k] * vreg[k].z;
        acc.w += wreg[k] * vreg[k].w;
    }

    // Parity-preserving xor reduction (16,8,4,2): lane0 = even-lane sum
    // (v0-3), lane1 = odd-lane sum (v4-7).
#pragma unroll
    for (int off = 16; off >= 2; off >>= 1) {
        acc.x += __shfl_xor_sync(0xFFFFFFFFu, acc.x, off);
        acc.y += __shfl_xor_sync(0xFFFFFFFFu, acc.y, off);
        acc.z += __shfl_xor_sync(0xFFFFFFFFu, acc.z, off);
        acc.w += __shfl_xor_sync(0xFFFFFFFFu, acc.w, off);
    }

    __shared__ float4 sred[8][2];  // [warp][parity]
    const int warp = threadIdx.x >> 5;
    const int lane = threadIdx.x & 31;
    if (lane < 2) sred[warp][lane] = acc;
    __syncthreads();

    if (threadIdx.x < 2) {
        const int p = threadIdx.x;  // 0 -> v0-3, 1 -> v4-7
        float4 sum = make_float4(0.f, 0.f, 0.f, 0.f);
#pragma unroll
        for (int w = 0; w < 8; w++) {
            sum.x += sred[w][p].x;  sum.y += sred[w][p].y;
            sum.z += sred[w][p].z;  sum.w += sred[w][p].w;
        }
        atomicAdd(&g_acc[4 * p + 0], (double)sum.x);
        atomicAdd(&g_acc[4 * p + 1], (double)sum.y);
        atomicAdd(&g_acc[4 * p + 2], (double)sum.z);
        atomicAdd(&g_acc[4 * p + 3], (double)sum.w);
    }

    // Last-block-done: fused finalize + state reset (replay-deterministic).
    __shared__ bool is_last;
    __threadfence();
    if (threadIdx.x == 0) {
        unsigned int old = atomicInc(&g_count, (unsigned int)(nblocks - 1));
        is_last = (old == (unsigned int)(nblocks - 1));
    }
    __syncthreads();

    if (is_last && threadIdx.x < 8) {
        const double val = atomicAdd(&g_acc[threadIdx.x], 0.0);
        out[threadIdx.x] = (float)(val * (1.0 / 6.0));  // fold quad weight
        g_acc[threadIdx.x] = 0.0;
    }
}

extern "C" void kernel_launch(void* const* d_in, const int* in_sizes, int n_in,
                              void* d_out, int out_size) {
    const float* nodal_values = (const float*)d_in[0];
    const float* coords       = (const float*)d_in[1];
    const int*   elements     = (const int*)d_in[2];
    float* out = (float*)d_out;

    const int n_elements = in_sizes[2] / 3;
    const int n_nodes    = in_sizes[1] / 2;
    const int n_f4       = n_nodes * 2;
    const int n_val_lines = (n_nodes * 8 * 4 + 127) / 128;  // 128B lines of vals

    phase1_kernel<<<2048, 256>>>(coords, elements,
                                 reinterpret_cast<const char*>(nodal_values),
                                 n_elements, n_val_lines);

    const int p2_blocks = (n_f4 + 256 * P2_UNROLL - 1) / (256 * P2_UNROLL);  // 977
    phase2_kernel<<<p2_blocks, 256>>>(
        reinterpret_cast<const float4*>(nodal_values), out, n_f4, p2_blocks);
}

// round 11
// speedup vs baseline: 1.0166x; 1.0166x over previous
#include <cuda_runtime.h>

// Per-node weight accumulator. Zero at module load; phase 2 re-zeroes after
// consuming, so every graph replay starts from zeros.
__device__ __align__(16) float g_w[4 * 1024 * 1024];
__device__ double g_acc[8];
__device__ unsigned int g_count;

// ---------------- Phase 1: det(J) scattered to node weights -----------------
// Grid-stride, atomics interleaved per iteration. Measured-best shape (R7);
// do not add anything to this loop — the LSU/L2 path is saturated.
__global__ __launch_bounds__(256) void phase1_kernel(
    const float* __restrict__ coords,    // (N_NODES, 2)
    const int*   __restrict__ elements,  // (E, 3)
    int n_elements)
{
    const int stride = gridDim.x * blockDim.x;
    for (int e = blockIdx.x * blockDim.x + threadIdx.x; e < n_elements; e += stride) {
        const int i0 = __ldcs(elements + 3 * e + 0);
        const int i1 = __ldcs(elements + 3 * e + 1);
        const int i2 = __ldcs(elements + 3 * e + 2);

        const float2 c0 = *reinterpret_cast<const float2*>(coords + 2 * i0);
        const float2 c1 = *reinterpret_cast<const float2*>(coords + 2 * i1);
        const float2 c2 = *reinterpret_cast<const float2*>(coords + 2 * i2);

        // det(J) for Tri3; quad weight 1/6 folded into finalize.
        const float det = (c1.x - c0.x) * (c2.y - c0.y)
                        - (c1.y - c0.y) * (c2.x - c0.x);

        atomicAdd(&g_w[i0], det);   // REDG.F32, no return
        atomicAdd(&g_w[i1], det);
        atomicAdd(&g_w[i2], det);
    }
}

// ---------------- Phase 2: dense dot  out[v] = (1/6) sum_n w[n]*vals[n][v] ---
// nodal_values viewed as 2*N float4s. Even float4 j -> v0..3 of node j/2,
// odd j -> v4..7. Thread parity == j parity (T even), so each thread always
// accumulates the same 4-value group; xor-reduce preserves parity.
// Launched with T*P2_UNROLL == n_f4 when possible -> guard-free fast path.
static const int P2_UNROLL = 8;
static const int P2_BLOCKS = 1024;   // 2^18 threads; x8 = 2^21 = n_f4 exactly

__global__ __launch_bounds__(256) void phase2_kernel(
    const float4* __restrict__ vals4,  // 2*N_NODES float4s
    float* __restrict__ out,
    int n_f4, int nblocks)
{
    const int T = nblocks * 256;
    const int t = blockIdx.x * 256 + threadIdx.x;

    float  wreg[P2_UNROLL];
    float4 vreg[P2_UNROLL];

    if (n_f4 == T * P2_UNROLL) {
        // Exact-fit fast path: no guards, clean front-batch of 16 loads.
#pragma unroll
        for (int k = 0; k < P2_UNROLL; k++) {
            const int j = t + k * T;
            wreg[k] = g_w[j >> 1];
            vreg[k] = vals4[j];
        }
        if ((t & 1) == 0) {   // even thread owns even j=2n -> every node once
#pragma unroll
            for (int k = 0; k < P2_UNROLL; k++)
                g_w[(t + k * T) >> 1] = 0.0f;
        }
    } else {
#pragma unroll
        for (int k = 0; k < P2_UNROLL; k++) {
            const int j = t + k * T;
            if (j < n_f4) {
                wreg[k] = g_w[j >> 1];
                vreg[k] = vals4[j];
            } else {
                wreg[k] = 0.0f;
                vreg[k] = make_float4(0.f, 0.f, 0.f, 0.f);
            }
        }
        if ((t & 1) == 0) {
#pragma unroll
            for (int k = 0; k < P2_UNROLL; k++) {
                const int j = t + k * T;
                if (j < n_f4) g_w[j >> 1] = 0.0f;
            }
        }
    }

    float4 acc = make_float4(0.f, 0.f, 0.f, 0.f);
#pragma unroll
    for (int k = 0; k < P2_UNROLL; k++) {
        acc.x += wreg[k] * vreg[k].x;
        acc.y += wreg[k] * vreg[k].y;
        acc.z += wreg[k] * vreg[k].z;
        acc.w += wreg[k] * vreg[k].w;
    }

    // Parity-preserving xor reduction (16,8,4,2): lane0 = even-lane sum
    // (v0-3), lane1 = odd-lane sum (v4-7).
#pragma unroll
    for (int off = 16; off >= 2; off >>= 1) {
        acc.x += __shfl_xor_sync(0xFFFFFFFFu, acc.x, off);
        acc.y += __shfl_xor_sync(0xFFFFFFFFu, acc.y, off);
        acc.z += __shfl_xor_sync(0xFFFFFFFFu, acc.z, off);
        acc.w += __shfl_xor_sync(0xFFFFFFFFu, acc.w, off);
    }

    __shared__ float4 sred[8][2];  // [warp][parity]
    const int warp = threadIdx.x >> 5;
    const int lane = threadIdx.x & 31;
    if (lane < 2) sred[warp][lane] = acc;
    __syncthreads();

    if (threadIdx.x < 2) {
        const int p = threadIdx.x;  // 0 -> v0-3, 1 -> v4-7
        float4 sum = make_float4(0.f, 0.f, 0.f, 0.f);
#pragma unroll
        for (int w = 0; w < 8; w++) {
            sum.x += sred[w][p].x;  sum.y += sred[w][p].y;
            sum.z += sred[w][p].z;  sum.w += sred[w][p].w;
        }
        atomicAdd(&g_acc[4 * p + 0], (double)sum.x);
        atomicAdd(&g_acc[4 * p + 1], (double)sum.y);
        atomicAdd(&g_acc[4 * p + 2], (double)sum.z);
        atomicAdd(&g_acc[4 * p + 3], (double)sum.w);
    }

    // Last-block-done: fused finalize + state reset (replay-deterministic).
    __shared__ bool is_last;
    __threadfence();
    if (threadIdx.x == 0) {
        unsigned int old = atomicInc(&g_count, (unsigned int)(nblocks - 1));
        is_last = (old == (unsigned int)(nblocks - 1));
    }
    __syncthreads();

    if (is_last && threadIdx.x < 8) {
        const double val = atomicAdd(&g_acc[threadIdx.x], 0.0);
        out[threadIdx.x] = (float)(val * (1.0 / 6.0));  // fold quad weight
        g_acc[threadIdx.x] = 0.0;
    }
}

extern "C" void kernel_launch(void* const* d_in, const int* in_sizes, int n_in,
                              void* d_out, int out_size) {
    const float* nodal_values = (const float*)d_in[0];
    const float* coords       = (const float*)d_in[1];
    const int*   elements     = (const int*)d_in[2];
    float* out = (float*)d_out;

    const int n_elements = in_sizes[2] / 3;
    const int n_nodes    = in_sizes[1] / 2;
    const int n_f4       = n_nodes * 2;

    phase1_kernel<<<2048, 256>>>(coords, elements, n_elements);

    // Prefer the exact-fit grid (2^18 threads x 8 = 2^21 = n_f4 for 1M nodes);
    // otherwise fall back to covering grid with guards.
    int p2_blocks = P2_BLOCKS;
    if (p2_blocks * 256 * P2_UNROLL < n_f4)
        p2_blocks = (n_f4 + 256 * P2_UNROLL - 1) / (256 * P2_UNROLL);
    phase2_kernel<<<p2_blocks, 256>>>(
        reinterpret_cast<const float4*>(nodal_values), out, n_f4, p2_blocks);
}

// round 12
// speedup vs baseline: 1.5069x; 1.4824x over previous
#include <cuda_runtime.h>

// Per-node weight accumulator. Zero at module load; phase 2 re-zeroes after
// consuming, so every graph replay starts from zeros.
__device__ float g_w[4 * 1024 * 1024];
__device__ double g_acc[8];
__device__ unsigned int g_count;

// ---------------- Phase 1: per-element det(J) scattered to node weights -----
// Grid-stride; atomics interleaved per iteration pipeline under the next
// iteration's loads. Element stream uses __ldcs (evict-first) to keep L1
// capacity for the random coord gathers. The 1/6 factor is folded into
// the finalize.
__global__ __launch_bounds__(256) void phase1_kernel(
    const float* __restrict__ coords,    // (N_NODES, 2)
    const int*   __restrict__ elements,  // (E, 3)
    int n_elements)
{
    const int stride = gridDim.x * blockDim.x;
    for (int e = blockIdx.x * blockDim.x + threadIdx.x; e < n_elements; e += stride) {
        const int i0 = __ldcs(elements + 3 * e + 0);
        const int i1 = __ldcs(elements + 3 * e + 1);
        const int i2 = __ldcs(elements + 3 * e + 2);

        const float2 c0 = *reinterpret_cast<const float2*>(coords + 2 * i0);
        const float2 c1 = *reinterpret_cast<const float2*>(coords + 2 * i1);
        const float2 c2 = *reinterpret_cast<const float2*>(coords + 2 * i2);

        // det(J) for Tri3 (scale by 1/6 deferred to finalize).
        const float det = (c1.x - c0.x) * (c2.y - c0.y)
                        - (c1.y - c0.y) * (c2.x - c0.x);

        atomicAdd(&g_w[i0], det);   // REDG.F32, no return
        atomicAdd(&g_w[i1], det);
        atomicAdd(&g_w[i2], det);
    }
}

// ---------------- Phase 2: dense dot  out[v] = (1/6) sum_n w[n]*vals[n][v] ---
// nodal_values viewed as 2*N float4s. Even float4 j -> v0..3 of node j/2,
// odd j -> v4..7. Thread parity == j parity (stride is even), so each thread
// always accumulates the same 4-value group; xor-reduce preserves parity.
static const int P2_UNROLL = 8;

__global__ __launch_bounds__(256) void phase2_kernel(
    const float4* __restrict__ vals4,  // 2*N_NODES float4s
    float* __restrict__ out,
    int n_f4, int nblocks)
{
    const int T = nblocks * 256;  // total threads (even)
    const int t = blockIdx.x * 256 + threadIdx.x;

    // Front-batched guarded loads: up to 16 independent loads in flight.
    float  wreg[P2_UNROLL];
    float4 vreg[P2_UNROLL];
#pragma unroll
    for (int k = 0; k < P2_UNROLL; k++) {
        const int j = t + k * T;
        if (j < n_f4) {
            wreg[k] = g_w[j >> 1];
            vreg[k] = vals4[j];
        } else {
            wreg[k] = 0.0f;
            vreg[k] = make_float4(0.f, 0.f, 0.f, 0.f);
        }
    }

    // Zero w for next replay: even threads own even j = 2n -> every node once.
    if ((t & 1) == 0) {
#pragma unroll
        for (int k = 0; k < P2_UNROLL; k++) {
            const int j = t + k * T;
            if (j < n_f4) g_w[j >> 1] = 0.0f;
        }
    }

    float4 acc = make_float4(0.f, 0.f, 0.f, 0.f);
#pragma unroll
    for (int k = 0; k < P2_UNROLL; k++) {
        acc.x += wreg[k] * vreg[k].x;
        acc.y += wreg[k] * vreg[k].y;
        acc.z += wreg[k] * vreg[k].z;
        acc.w += wreg[k] * vreg[k].w;
    }

    // Parity-preserving xor reduction (offsets 16,8,4,2): lane0 = even lanes
    // (v0-3), lane1 = odd lanes (v4-7).
#pragma unroll
    for (int off = 16; off >= 2; off >>= 1) {
        acc.x += __shfl_xor_sync(0xFFFFFFFFu, acc.x, off);
        acc.y += __shfl_xor_sync(0xFFFFFFFFu, acc.y, off);
        acc.z += __shfl_xor_sync(0xFFFFFFFFu, acc.z, off);
        acc.w += __shfl_xor_sync(0xFFFFFFFFu, acc.w, off);
    }

    __shared__ float4 sred[8][2];  // [warp][parity]
    const int warp = threadIdx.x >> 5;
    const int lane = threadIdx.x & 31;
    if (lane < 2) sred[warp][lane] = acc;
    __syncthreads();

    if (threadIdx.x < 2) {
        const int p = threadIdx.x;  // 0 -> v0-3, 1 -> v4-7
        float4 sum = make_float4(0.f, 0.f, 0.f, 0.f);
#pragma unroll
        for (int w = 0; w < 8; w++) {
            sum.x += sred[w][p].x;  sum.y += sred[w][p].y;
            sum.z += sred[w][p].z;  sum.w += sred[w][p].w;
        }
        atomicAdd(&g_acc[4 * p + 0], (double)sum.x);
        atomicAdd(&g_acc[4 * p + 1], (double)sum.y);
        atomicAdd(&g_acc[4 * p + 2], (double)sum.z);
        atomicAdd(&g_acc[4 * p + 3], (double)sum.w);
    }

    // Last-block-done: fused finalize + state reset (replay-deterministic).
    __shared__ bool is_last;
    __threadfence();
    if (threadIdx.x == 0) {
        unsigned int old = atomicInc(&g_count, (unsigned int)(nblocks - 1));
        is_last = (old == (unsigned int)(nblocks - 1));
    }
    __syncthreads();

    if (is_last && threadIdx.x < 8) {
        const double val = atomicAdd(&g_acc[threadIdx.x], 0.0);
        out[threadIdx.x] = (float)(val * (1.0 / 6.0));  // fold quad weight here
        g_acc[threadIdx.x] = 0.0;
    }
}

extern "C" void kernel_launch(void* const* d_in, const int* in_sizes, int n_in,
                              void* d_out, int out_size) {
    const float* nodal_values = (const float*)d_in[0];
    const float* coords       = (const float*)d_in[1];
    const int*   elements     = (const int*)d_in[2];
    float* out = (float*)d_out;

    const int n_elements = in_sizes[2] / 3;
    const int n_nodes    = in_sizes[1] / 2;
    const int n_f4       = n_nodes * 2;

    phase1_kernel<<<2048, 256>>>(coords, elements, n_elements);

    const int p2_blocks = (n_f4 + 256 * P2_UNROLL - 1) / (256 * P2_UNROLL);  // 977
    phase2_kernel<<<p2_blocks, 256>>>(
        reinterpret_cast<const float4*>(nodal_values), out, n_f4, p2_blocks);
}